// round 2
// baseline (speedup 1.0000x reference)
#include <cuda_runtime.h>

#define Nn   100000
#define Ecnt 1600000
#define ETOT (Ecnt + Nn)
#define Dh   64
#define NB_SCAN ((Nn + 255) / 256)   // 391

// ---------------- scratch (device globals: allocation-free) ----------------
__device__ float g_xl[Nn * Dh];
__device__ float g_xr[Nn * Dh];
__device__ float g_x [Nn * Dh];
__device__ int   g_deg[Nn];
__device__ int   g_ptr[Nn];
__device__ int   g_cur[Nn];
__device__ int   g_srcA[ETOT];
__device__ int   g_bsum[512];
__device__ int   g_bscan[512];

// ---------------- CSR build ----------------
__global__ void zero_deg_kernel() {
    int i = blockIdx.x * blockDim.x + threadIdx.x;
    if (i < Nn) g_deg[i] = 0;
}

__global__ void hist_kernel(const int* __restrict__ ei) {
    int e = blockIdx.x * blockDim.x + threadIdx.x;
    if (e >= ETOT) return;
    int dst = (e < Ecnt) ? ei[Ecnt + e] : (e - Ecnt);
    atomicAdd(&g_deg[dst], 1);
}

__device__ __forceinline__ int block_excl_scan(int v, int* warp_sums) {
    int lane = threadIdx.x & 31, wid = threadIdx.x >> 5;
    int x = v;
#pragma unroll
    for (int off = 1; off < 32; off <<= 1) {
        int t = __shfl_up_sync(0xffffffffu, x, off);
        if (lane >= off) x += t;
    }
    if (lane == 31) warp_sums[wid] = x;
    __syncthreads();
    if (wid == 0) {
        int nw = blockDim.x >> 5;
        int w = (lane < nw) ? warp_sums[lane] : 0;
#pragma unroll
        for (int off = 1; off < 32; off <<= 1) {
            int t = __shfl_up_sync(0xffffffffu, w, off);
            if (lane >= off) w += t;
        }
        warp_sums[lane] = w;
    }
    __syncthreads();
    int woff = wid ? warp_sums[wid - 1] : 0;
    return woff + x - v;
}

__global__ void scan1_kernel() {   // per-block totals of g_deg
    __shared__ int ws[32];
    int i = blockIdx.x * 256 + threadIdx.x;
    int v = (i < Nn) ? g_deg[i] : 0;
    int excl = block_excl_scan(v, ws);
    if (threadIdx.x == 255) g_bsum[blockIdx.x] = excl + v;
}

__global__ void scan2_kernel(int nb) {   // scan block totals (single block, nb<=512)
    __shared__ int ws[32];
    int i = threadIdx.x;
    int v = (i < nb) ? g_bsum[i] : 0;
    int excl = block_excl_scan(v, ws);
    if (i < nb) g_bscan[i] = excl;
}

__global__ void scan3_kernel() {   // final offsets -> g_ptr, g_cur
    __shared__ int ws[32];
    int i = blockIdx.x * 256 + threadIdx.x;
    int v = (i < Nn) ? g_deg[i] : 0;
    int excl = block_excl_scan(v, ws) + g_bscan[blockIdx.x];
    if (i < Nn) { g_ptr[i] = excl; g_cur[i] = excl; }
}

__global__ void scatter_kernel(const int* __restrict__ ei) {
    int e = blockIdx.x * blockDim.x + threadIdx.x;
    if (e >= ETOT) return;
    int src, dst;
    if (e < Ecnt) { src = ei[e]; dst = ei[Ecnt + e]; }
    else          { src = dst = e - Ecnt; }
    int pos = atomicAdd(&g_cur[dst], 1);
    g_srcA[pos] = src;
}

// ---------------- dense projections: Y = X @ W + b ----------------
// src_sel: 0 = external input X (layer 0), 1 = g_x (hidden state)
// dst_sel: 0 = g_xl, 1 = g_xr
template <int CIN>
__global__ void __launch_bounds__(128) matmul_kernel(
    const float* __restrict__ Xext, int src_sel, int dst_sel,
    const float* __restrict__ W, const float* __restrict__ B)
{
    __shared__ float sW[CIN * Dh];
    for (int i = threadIdx.x; i < CIN * Dh; i += 128) sW[i] = W[i];
    __syncthreads();
    int n = blockIdx.x * 128 + threadIdx.x;
    if (n >= Nn) return;
    const float* X = src_sel ? g_x : Xext;
    float acc[Dh];
#pragma unroll
    for (int d = 0; d < Dh; ++d) acc[d] = __ldg(&B[d]);
    const float4* xrow = (const float4*)(X + (size_t)n * CIN);
#pragma unroll 2
    for (int k4 = 0; k4 < CIN / 4; ++k4) {
        float4 xv = xrow[k4];
        const float* w0 = &sW[(k4 * 4) * Dh];
#pragma unroll
        for (int j = 0; j < 4; ++j) {
            float xs = (j == 0) ? xv.x : (j == 1) ? xv.y : (j == 2) ? xv.z : xv.w;
            const float4* wr = (const float4*)(w0 + j * Dh);
#pragma unroll
            for (int d4 = 0; d4 < 16; ++d4) {
                float4 w = wr[d4];
                acc[d4 * 4 + 0] = fmaf(xs, w.x, acc[d4 * 4 + 0]);
                acc[d4 * 4 + 1] = fmaf(xs, w.y, acc[d4 * 4 + 1]);
                acc[d4 * 4 + 2] = fmaf(xs, w.z, acc[d4 * 4 + 2]);
                acc[d4 * 4 + 3] = fmaf(xs, w.w, acc[d4 * 4 + 3]);
            }
        }
    }
    float4* yrow = (float4*)((dst_sel ? g_xr : g_xl) + (size_t)n * Dh);
#pragma unroll
    for (int d4 = 0; d4 < 16; ++d4)
        yrow[d4] = make_float4(acc[d4 * 4], acc[d4 * 4 + 1], acc[d4 * 4 + 2], acc[d4 * 4 + 3]);
}

// ---------------- fused edge softmax + aggregate + epilogue ----------------
// One warp per destination node. lane covers feature pair d0 = 2*lane.
// Head h = d0 / C, i.e. G = C/2 lanes per head. No max-subtraction: attention
// logits are bounded far below fp32 exp overflow for this data distribution
// (clamped at 80 as a pure safety net).
// LAST: writes to external out (d_out) and applies L2 norm + final relu;
// otherwise writes to g_x.
template <int H, int RELU, int LAST>
__global__ void __launch_bounds__(256) gat_agg_kernel(
    const float* __restrict__ att, const float* __restrict__ bias,
    float* __restrict__ out_ext)
{
    constexpr int C = Dh / H;
    constexpr int G = C / 2;          // lanes per head (8 for H=4, 32 for H=1)
    int warp = (blockIdx.x * blockDim.x + threadIdx.x) >> 5;
    int lane = threadIdx.x & 31;
    if (warp >= Nn) return;
    int n = warp;
    int d0 = lane * 2;

    float2 xr = ((const float2*)g_xr)[n * 32 + lane];
    float a0 = __ldg(&att[d0]), a1 = __ldg(&att[d0 + 1]);

    int beg = g_ptr[n];
    int end = beg + g_deg[n];

    float accx = 0.f, accy = 0.f, den = 0.f;
    int e = beg;
    int    src_n = 0;
    float2 xl_n  = make_float2(0.f, 0.f);
    if (e < end) {
        src_n = g_srcA[e];
        xl_n  = ((const float2*)g_xl)[src_n * 32 + lane];
    }
    while (e < end) {
        float2 xl = xl_n;
        int e2 = e + 1;
        if (e2 < end) {                         // software prefetch (MLP=2)
            src_n = g_srcA[e2];
            xl_n  = ((const float2*)g_xl)[src_n * 32 + lane];
        }
        float s0 = xl.x + xr.x; s0 = (s0 > 0.f) ? s0 : 0.2f * s0;
        float s1 = xl.y + xr.y; s1 = (s1 > 0.f) ? s1 : 0.2f * s1;
        float p = s0 * a0 + s1 * a1;
#pragma unroll
        for (int off = 1; off < G; off <<= 1)
            p += __shfl_xor_sync(0xffffffffu, p, off);
        float ev = __expf(fminf(p, 80.f));      // all lanes of a head share ev
        den += ev;
        accx = fmaf(xl.x, ev, accx);
        accy = fmaf(xl.y, ev, accy);
        e = e2;
    }

    float invd = 1.0f / (den + 1e-16f);
    float vx = accx * invd + __ldg(&bias[d0]);
    float vy = accy * invd + __ldg(&bias[d0 + 1]);
    if (RELU) { vx = fmaxf(vx, 0.f); vy = fmaxf(vy, 0.f); }

    // L1 normalize over the 64-wide row
    float s = fabsf(vx) + fabsf(vy);
#pragma unroll
    for (int off = 16; off; off >>= 1) s += __shfl_xor_sync(0xffffffffu, s, off);
    float inv1 = 1.0f / fmaxf(s, 1e-12f);
    vx *= inv1; vy *= inv1;

    if (LAST) {   // L2 normalize + final relu
        float q = vx * vx + vy * vy;
#pragma unroll
        for (int off = 16; off; off >>= 1) q += __shfl_xor_sync(0xffffffffu, q, off);
        float inv2 = 1.0f / fmaxf(sqrtf(q), 1e-12f);
        vx = fmaxf(vx * inv2, 0.f);
        vy = fmaxf(vy * inv2, 0.f);
        ((float2*)out_ext)[n * 32 + lane] = make_float2(vx, vy);
    } else {
        ((float2*)g_x)[n * 32 + lane] = make_float2(vx, vy);
    }
}

// ---------------- host ----------------
static void run_csr_build(const int* ei) {
    int gridE = (ETOT + 255) / 256;
    int gridN = (Nn + 255) / 256;
    zero_deg_kernel<<<gridN, 256>>>();
    hist_kernel<<<gridE, 256>>>(ei);
    scan1_kernel<<<NB_SCAN, 256>>>();
    scan2_kernel<<<1, 512>>>(NB_SCAN);
    scan3_kernel<<<NB_SCAN, 256>>>();
    scatter_kernel<<<gridE, 256>>>(ei);
}

extern "C" void kernel_launch(void* const* d_in, const int* in_sizes, int n_in,
                              void* d_out, int out_size)
{
    const float* x0  = (const float*)d_in[0];
    const int*   ei0 = (const int*)d_in[1];
    const int*   ei1 = (const int*)d_in[2];
    const int*   ei2 = (const int*)d_in[3];

    int gridMM  = (Nn + 127) / 128;
    int gridAgg = (Nn * 32 + 255) / 256;

    // ---- layer 0 (CIN=128, H=4, relu) ----
    {
        const float* Wl   = (const float*)d_in[4];
        const float* bl   = (const float*)d_in[5];
        const float* Wr   = (const float*)d_in[6];
        const float* br   = (const float*)d_in[7];
        const float* att  = (const float*)d_in[8];
        const float* bias = (const float*)d_in[9];
        matmul_kernel<128><<<gridMM, 128>>>(x0, 0, 0, Wl, bl);
        matmul_kernel<128><<<gridMM, 128>>>(x0, 0, 1, Wr, br);
        run_csr_build(ei0);
        gat_agg_kernel<4, 1, 0><<<gridAgg, 256>>>(att, bias, nullptr);
    }
    // ---- layer 1 (CIN=64, H=4, relu) ----
    {
        const float* Wl   = (const float*)d_in[10];
        const float* bl   = (const float*)d_in[11];
        const float* Wr   = (const float*)d_in[12];
        const float* br   = (const float*)d_in[13];
        const float* att  = (const float*)d_in[14];
        const float* bias = (const float*)d_in[15];
        matmul_kernel<64><<<gridMM, 128>>>(nullptr, 1, 0, Wl, bl);
        matmul_kernel<64><<<gridMM, 128>>>(nullptr, 1, 1, Wr, br);
        run_csr_build(ei1);
        gat_agg_kernel<4, 1, 0><<<gridAgg, 256>>>(att, bias, nullptr);
    }
    // ---- layer 2 (CIN=64, H=1, no relu, + L2-norm + final relu) ----
    {
        const float* Wl   = (const float*)d_in[16];
        const float* bl   = (const float*)d_in[17];
        const float* Wr   = (const float*)d_in[18];
        const float* br   = (const float*)d_in[19];
        const float* att  = (const float*)d_in[20];
        const float* bias = (const float*)d_in[21];
        matmul_kernel<64><<<gridMM, 128>>>(nullptr, 1, 0, Wl, bl);
        matmul_kernel<64><<<gridMM, 128>>>(nullptr, 1, 1, Wr, br);
        run_csr_build(ei2);
        gat_agg_kernel<1, 0, 1><<<gridAgg, 256>>>(att, bias, (float*)d_out);
    }
}

// round 3
// speedup vs baseline: 1.2005x; 1.2005x over previous
#include <cuda_runtime.h>

#define Nn    100000
#define Ecnt  1600000
#define ETOT  (Ecnt + Nn)          // 1,700,000 (divisible by 4)
#define Dh    64
#define NB    391                  // ceil(Nn/256)
#define MMB   782                  // ceil(Nn/128) matmul blocks per weight
#define HISTB 3321                 // ceil((ETOT/4)/128) edge-chunk blocks
#define AGGB  12500                // Nn warps / 8 warps per 256-thr block

// ---------------- scratch (device globals: allocation-free) ----------------
__device__ __align__(16) float g_xl[Nn * Dh];
__device__ __align__(16) float g_xr[Nn * Dh];
__device__ __align__(16) float g_x [Nn * Dh];
__device__ int  g_deg[Nn];
__device__ int  g_ptr[Nn];
__device__ int  g_end[Nn];
__device__ __align__(16) int g_eoff[ETOT];
__device__ int  g_srcA[ETOT];
__device__ int  g_bsum[512];

// ---------------- helpers ----------------
__device__ __forceinline__ int block_excl_scan(int v, int* warp_sums) {
    int lane = threadIdx.x & 31, wid = threadIdx.x >> 5;
    int x = v;
#pragma unroll
    for (int off = 1; off < 32; off <<= 1) {
        int t = __shfl_up_sync(0xffffffffu, x, off);
        if (lane >= off) x += t;
    }
    if (lane == 31) warp_sums[wid] = x;
    __syncthreads();
    if (wid == 0) {
        int nw = blockDim.x >> 5;
        int w = (lane < nw) ? warp_sums[lane] : 0;
#pragma unroll
        for (int off = 1; off < 32; off <<= 1) {
            int t = __shfl_up_sync(0xffffffffu, w, off);
            if (lane >= off) w += t;
        }
        warp_sums[lane] = w;
    }
    __syncthreads();
    int woff = wid ? warp_sums[wid - 1] : 0;
    return woff + x - v;
}

__global__ void zero_deg_kernel() {
    int i = blockIdx.x * blockDim.x + threadIdx.x;
    if (i < Nn) g_deg[i] = 0;
}

// ---------------- fused: dual matmul (Wl & Wr) + histogram ----------------
// blocks [0, MMB)        -> xl = X@Wl + bl
// blocks [MMB, 2*MMB)    -> xr = X@Wr + br
// blocks [2*MMB, ...)    -> degree histogram + per-edge offset (atomic return)
template <int CIN>
__global__ void __launch_bounds__(128) fusedA_kernel(
    const float* __restrict__ Xext, int src_sel,
    const float* __restrict__ Wl, const float* __restrict__ bl,
    const float* __restrict__ Wr, const float* __restrict__ br,
    const int* __restrict__ ei)
{
    __shared__ float sW[CIN * Dh];
    if (blockIdx.x < 2 * MMB) {
        int sel = blockIdx.x >= MMB;
        const float* W = sel ? Wr : Wl;
        const float* B = sel ? br : bl;
        float* Y = sel ? g_xr : g_xl;
        for (int i = threadIdx.x; i < CIN * Dh; i += 128) sW[i] = W[i];
        __syncthreads();
        int n = (blockIdx.x - sel * MMB) * 128 + threadIdx.x;
        if (n >= Nn) return;
        const float* X = src_sel ? g_x : Xext;
        float acc[Dh];
#pragma unroll
        for (int d = 0; d < Dh; ++d) acc[d] = __ldg(&B[d]);
        const float4* xrow = (const float4*)(X + (size_t)n * CIN);
#pragma unroll 2
        for (int k4 = 0; k4 < CIN / 4; ++k4) {
            float4 xv = xrow[k4];
            const float* w0 = &sW[(k4 * 4) * Dh];
#pragma unroll
            for (int j = 0; j < 4; ++j) {
                float xs = (j == 0) ? xv.x : (j == 1) ? xv.y : (j == 2) ? xv.z : xv.w;
                const float4* wr = (const float4*)(w0 + j * Dh);
#pragma unroll
                for (int d4 = 0; d4 < 16; ++d4) {
                    float4 w = wr[d4];
                    acc[d4 * 4 + 0] = fmaf(xs, w.x, acc[d4 * 4 + 0]);
                    acc[d4 * 4 + 1] = fmaf(xs, w.y, acc[d4 * 4 + 1]);
                    acc[d4 * 4 + 2] = fmaf(xs, w.z, acc[d4 * 4 + 2]);
                    acc[d4 * 4 + 3] = fmaf(xs, w.w, acc[d4 * 4 + 3]);
                }
            }
        }
        float4* yrow = (float4*)(Y + (size_t)n * Dh);
#pragma unroll
        for (int d4 = 0; d4 < 16; ++d4)
            yrow[d4] = make_float4(acc[d4 * 4], acc[d4 * 4 + 1], acc[d4 * 4 + 2], acc[d4 * 4 + 3]);
    } else {
        int t = (blockIdx.x - 2 * MMB) * 128 + threadIdx.x;
        int e = t * 4;
        if (e >= ETOT) return;
        int d0, d1, d2, d3;
        if (e < Ecnt) {                       // Ecnt % 4 == 0: no straddle
            int4 dv = *(const int4*)(ei + Ecnt + e);
            d0 = dv.x; d1 = dv.y; d2 = dv.z; d3 = dv.w;
        } else {
            d0 = e - Ecnt; d1 = d0 + 1; d2 = d0 + 2; d3 = d0 + 3;
        }
        int4 offs;
        offs.x = atomicAdd(&g_deg[d0], 1);
        offs.y = atomicAdd(&g_deg[d1], 1);
        offs.z = atomicAdd(&g_deg[d2], 1);
        offs.w = atomicAdd(&g_deg[d3], 1);
        *(int4*)(g_eoff + e) = offs;
    }
}

// ---------------- scan: per-block partials, then redundant-scan finish ----
__global__ void __launch_bounds__(256) scanA_kernel() {
    __shared__ int ws[32];
    int i = blockIdx.x * 256 + threadIdx.x;
    int v = (i < Nn) ? g_deg[i] : 0;
    int excl = block_excl_scan(v, ws);
    if (threadIdx.x == 255) g_bsum[blockIdx.x] = excl + v;
}

__global__ void __launch_bounds__(512) scanB_kernel() {
    __shared__ int ws[32];
    __shared__ int sc[512];
    int t = threadIdx.x;
    int v = (t < NB) ? g_bsum[t] : 0;            // redundant scan of partials
    int excl = block_excl_scan(v, ws);
    sc[t] = excl;
    __syncthreads();
    int block_off = sc[blockIdx.x];
    __syncthreads();
    int i = blockIdx.x * 256 + t;                // only t<256 map to nodes
    int v2 = (t < 256 && i < Nn) ? g_deg[i] : 0;
    int excl2 = block_excl_scan(v2, ws);
    if (t < 256 && i < Nn) {
        int p = block_off + excl2;
        g_ptr[i] = p;
        g_end[i] = p + v2;
    }
}

// ---------------- scatter (atomic-free, vectorized) ----------------
__global__ void __launch_bounds__(128) scatter_kernel(const int* __restrict__ ei) {
    int t = blockIdx.x * 128 + threadIdx.x;
    int e = t * 4;
    if (e >= ETOT) return;
    int4 off4 = *(const int4*)(g_eoff + e);
    if (e < Ecnt) {
        int4 sv = *(const int4*)(ei + e);
        int4 dv = *(const int4*)(ei + Ecnt + e);
        g_srcA[g_ptr[dv.x] + off4.x] = sv.x;
        g_srcA[g_ptr[dv.y] + off4.y] = sv.y;
        g_srcA[g_ptr[dv.z] + off4.z] = sv.z;
        g_srcA[g_ptr[dv.w] + off4.w] = sv.w;
    } else {
        int b = e - Ecnt;
        g_srcA[g_ptr[b]     + off4.x] = b;
        g_srcA[g_ptr[b + 1] + off4.y] = b + 1;
        g_srcA[g_ptr[b + 2] + off4.z] = b + 2;
        g_srcA[g_ptr[b + 3] + off4.w] = b + 3;
    }
}

// ---------------- fused edge softmax + aggregate + epilogue ----------------
// One warp per destination node; two half-warps process 2 edges/iteration.
// Each sublane (0..15) covers 4 features (float4). src indices batch-loaded
// (32 at a time) and broadcast via shfl. No segment-max pass: logits bounded
// far below fp32 exp overflow for this distribution (clamped at 80 as safety).
template <int H, int RELU, int LAST, int ZNEXT>
__global__ void __launch_bounds__(256) gat_agg_kernel(
    const float* __restrict__ att, const float* __restrict__ bias,
    float* __restrict__ out_ext)
{
    constexpr int C  = Dh / H;
    constexpr int G4 = C / 4;               // sublanes per head (4 for H=4, 16 for H=1)
    int gid  = blockIdx.x * 256 + threadIdx.x;
    if (ZNEXT && gid < Nn) g_deg[gid] = 0;  // zero deg for next layer's hist
    int warp = gid >> 5;
    int lane = threadIdx.x & 31;
    int half = lane >> 4, sub = lane & 15;
    int n = warp;                           // grid == Nn warps exactly

    float4 xr4 = ((const float4*)g_xr)[n * 16 + sub];
    float4 at4 = ((const float4*)att)[sub];

    int beg = g_ptr[n];
    int nE  = g_end[n] - beg;               // >= 1 (self loop)

    float4 acc = make_float4(0.f, 0.f, 0.f, 0.f);
    float den = 0.f;

    for (int base = 0; base < nE; base += 32) {
        int rem = nE - base; if (rem > 32) rem = 32;
        int sb = (lane < rem) ? g_srcA[beg + base + lane] : 0;
        for (int k = 0; k < rem; k += 2) {
            int my = k + half;
            bool valid = my < rem;
            int src = __shfl_sync(0xffffffffu, sb, valid ? my : 0);
            float4 xl = valid ? ((const float4*)g_xl)[src * 16 + sub]
                              : make_float4(0.f, 0.f, 0.f, 0.f);
            float s0 = xl.x + xr4.x; s0 = fmaxf(s0, 0.2f * s0);
            float s1 = xl.y + xr4.y; s1 = fmaxf(s1, 0.2f * s1);
            float s2 = xl.z + xr4.z; s2 = fmaxf(s2, 0.2f * s2);
            float s3 = xl.w + xr4.w; s3 = fmaxf(s3, 0.2f * s3);
            float p = s0 * at4.x;
            p = fmaf(s1, at4.y, p);
            p = fmaf(s2, at4.z, p);
            p = fmaf(s3, at4.w, p);
#pragma unroll
            for (int off = 1; off < G4; off <<= 1)
                p += __shfl_xor_sync(0xffffffffu, p, off);
            float ev = valid ? __expf(fminf(p, 80.f)) : 0.f;
            den += ev;
            acc.x = fmaf(xl.x, ev, acc.x);
            acc.y = fmaf(xl.y, ev, acc.y);
            acc.z = fmaf(xl.z, ev, acc.z);
            acc.w = fmaf(xl.w, ev, acc.w);
        }
    }
    // combine the two half-warps (both halves end up with full sums)
    den   += __shfl_xor_sync(0xffffffffu, den,   16);
    acc.x += __shfl_xor_sync(0xffffffffu, acc.x, 16);
    acc.y += __shfl_xor_sync(0xffffffffu, acc.y, 16);
    acc.z += __shfl_xor_sync(0xffffffffu, acc.z, 16);
    acc.w += __shfl_xor_sync(0xffffffffu, acc.w, 16);

    float invd = 1.0f / (den + 1e-16f);
    float4 b4 = ((const float4*)bias)[sub];
    float vx = acc.x * invd + b4.x;
    float vy = acc.y * invd + b4.y;
    float vz = acc.z * invd + b4.z;
    float vw = acc.w * invd + b4.w;
    if (RELU) {
        vx = fmaxf(vx, 0.f); vy = fmaxf(vy, 0.f);
        vz = fmaxf(vz, 0.f); vw = fmaxf(vw, 0.f);
    }
    // L1 normalize over 64 features (values identical across halves; reduce 16 sublanes)
    float s = fabsf(vx) + fabsf(vy) + fabsf(vz) + fabsf(vw);
#pragma unroll
    for (int off = 1; off < 16; off <<= 1) s += __shfl_xor_sync(0xffffffffu, s, off);
    float inv1 = 1.0f / fmaxf(s, 1e-12f);
    vx *= inv1; vy *= inv1; vz *= inv1; vw *= inv1;

    if (LAST) {   // L2 normalize + final relu
        float q = vx * vx + vy * vy + vz * vz + vw * vw;
#pragma unroll
        for (int off = 1; off < 16; off <<= 1) q += __shfl_xor_sync(0xffffffffu, q, off);
        float inv2 = 1.0f / fmaxf(sqrtf(q), 1e-12f);
        vx = fmaxf(vx * inv2, 0.f); vy = fmaxf(vy * inv2, 0.f);
        vz = fmaxf(vz * inv2, 0.f); vw = fmaxf(vw * inv2, 0.f);
    }
    float* outp = LAST ? out_ext : g_x;
    if (half == 0)
        ((float4*)outp)[n * 16 + sub] = make_float4(vx, vy, vz, vw);
}

// ---------------- host ----------------
extern "C" void kernel_launch(void* const* d_in, const int* in_sizes, int n_in,
                              void* d_out, int out_size)
{
    const float* x0  = (const float*)d_in[0];
    const int*   ei0 = (const int*)d_in[1];
    const int*   ei1 = (const int*)d_in[2];
    const int*   ei2 = (const int*)d_in[3];

    zero_deg_kernel<<<NB, 256>>>();

    // ---- layer 0 (CIN=128, H=4, relu) ----
    fusedA_kernel<128><<<2 * MMB + HISTB, 128>>>(
        x0, 0,
        (const float*)d_in[4], (const float*)d_in[5],
        (const float*)d_in[6], (const float*)d_in[7], ei0);
    scanA_kernel<<<NB, 256>>>();
    scanB_kernel<<<NB, 512>>>();
    scatter_kernel<<<HISTB, 128>>>(ei0);
    gat_agg_kernel<4, 1, 0, 1><<<AGGB, 256>>>(
        (const float*)d_in[8], (const float*)d_in[9], nullptr);

    // ---- layer 1 (CIN=64, H=4, relu) ----
    fusedA_kernel<64><<<2 * MMB + HISTB, 128>>>(
        nullptr, 1,
        (const float*)d_in[10], (const float*)d_in[11],
        (const float*)d_in[12], (const float*)d_in[13], ei1);
    scanA_kernel<<<NB, 256>>>();
    scanB_kernel<<<NB, 512>>>();
    scatter_kernel<<<HISTB, 128>>>(ei1);
    gat_agg_kernel<4, 1, 0, 1><<<AGGB, 256>>>(
        (const float*)d_in[14], (const float*)d_in[15], nullptr);

    // ---- layer 2 (CIN=64, H=1, no relu, + L2-norm + final relu) ----
    fusedA_kernel<64><<<2 * MMB + HISTB, 128>>>(
        nullptr, 1,
        (const float*)d_in[16], (const float*)d_in[17],
        (const float*)d_in[18], (const float*)d_in[19], ei2);
    scanA_kernel<<<NB, 256>>>();
    scanB_kernel<<<NB, 512>>>();
    scatter_kernel<<<HISTB, 128>>>(ei2);
    gat_agg_kernel<1, 0, 1, 0><<<AGGB, 256>>>(
        (const float*)d_in[20], (const float*)d_in[21], (float*)d_out);
}

// round 4
// speedup vs baseline: 1.2693x; 1.0573x over previous
#include <cuda_runtime.h>

#define Nn    100000
#define Ecnt  1600000
#define ETOT  (Ecnt + Nn)          // 1,700,000 (divisible by 4)
#define Dh    64
#define NB    391                  // ceil(Nn/256)
#define MMB   782                  // ceil(Nn/128) gemm node-tiles per weight
#define HISTB 3321                 // ceil((ETOT/4)/128) edge-chunk blocks
#define AGGB  12500                // Nn warps / 8 warps per 256-thr block
#define KC    32                   // GEMM k-chunk

// ---------------- scratch (device globals: allocation-free) ----------------
__device__ __align__(16) float g_xl[Nn * Dh];
__device__ __align__(16) float g_xr[Nn * Dh];
__device__ __align__(16) float g_x [Nn * Dh];
__device__ int  g_deg[Nn];
__device__ int  g_ptr[Nn];
__device__ int  g_end[Nn];
__device__ __align__(16) int g_eoff[ETOT];
__device__ int  g_srcA[ETOT];
__device__ int  g_bsum[512];

// ---------------- helpers ----------------
__device__ __forceinline__ int block_excl_scan(int v, int* warp_sums) {
    int lane = threadIdx.x & 31, wid = threadIdx.x >> 5;
    int x = v;
#pragma unroll
    for (int off = 1; off < 32; off <<= 1) {
        int t = __shfl_up_sync(0xffffffffu, x, off);
        if (lane >= off) x += t;
    }
    if (lane == 31) warp_sums[wid] = x;
    __syncthreads();
    if (wid == 0) {
        int nw = blockDim.x >> 5;
        int w = (lane < nw) ? warp_sums[lane] : 0;
#pragma unroll
        for (int off = 1; off < 32; off <<= 1) {
            int t = __shfl_up_sync(0xffffffffu, w, off);
            if (lane >= off) w += t;
        }
        warp_sums[lane] = w;
    }
    __syncthreads();
    int woff = wid ? warp_sums[wid - 1] : 0;
    return woff + x - v;
}

__global__ void zero_deg_kernel() {
    int i = blockIdx.x * blockDim.x + threadIdx.x;
    if (i < Nn) g_deg[i] = 0;
}

__device__ __forceinline__ unsigned long long pack2(float lo, float hi) {
    unsigned long long r;
    asm("mov.b64 %0, {%1, %2};" : "=l"(r) : "r"(__float_as_uint(lo)), "r"(__float_as_uint(hi)));
    return r;
}

// ---------------- fused: dual GEMM (Wl & Wr) + histogram ----------------
// blocks [0, MMB)      -> xl = X@Wl + bl   (128-node tile each)
// blocks [MMB, 2*MMB)  -> xr = X@Wr + br
// blocks [2*MMB, ...)  -> degree histogram + per-edge offset (atomic return)
// GEMM: thread = 4 nodes x 16 features, accumulators in packed f32x2,
// inner product via fma.rn.f32x2 (2 MACs/lane/instr -> 2x fp32 FMA ceiling).
template <int CIN>
__global__ void __launch_bounds__(128) fusedA_kernel(
    const float* __restrict__ Xext, int src_sel,
    const float* __restrict__ Wl, const float* __restrict__ bl,
    const float* __restrict__ Wr, const float* __restrict__ br,
    const int* __restrict__ ei)
{
    __shared__ float sW[KC * 64];        // W k-chunk
    __shared__ float sX[128 * 33];       // X tile (pad 33: conflict-free)
    if (blockIdx.x < 2 * MMB) {
        int sel = blockIdx.x >= MMB;
        const float* W = sel ? Wr : Wl;
        const float* B = sel ? br : bl;
        float* Y = sel ? g_xr : g_xl;
        const float* X = src_sel ? g_x : Xext;
        int node0 = (blockIdx.x - sel * MMB) * 128;
        int tid = threadIdx.x;
        int nr = tid >> 2;               // 0..31: nodes 4*nr .. 4*nr+3
        int fc = tid & 3;                // features [16*fc, 16*fc+16)

        unsigned long long acc[4][8];
        {
            unsigned long long b2[8];
#pragma unroll
            for (int p = 0; p < 8; ++p) {
                float2 bv = *(const float2*)&B[fc * 16 + 2 * p];
                b2[p] = pack2(bv.x, bv.y);
            }
#pragma unroll
            for (int j = 0; j < 4; ++j)
#pragma unroll
                for (int p = 0; p < 8; ++p) acc[j][p] = b2[p];
        }

        int lane8 = tid & 7, rbase = tid >> 3;   // X-tile loader mapping
        for (int kc = 0; kc < CIN / KC; ++kc) {
            // stage W chunk (coalesced float4)
#pragma unroll
            for (int i = 0; i < (KC * 64 / 4) / 128; ++i)
                ((float4*)sW)[tid + i * 128] =
                    ((const float4*)(W + kc * KC * 64))[tid + i * 128];
            // stage X chunk: 8 threads cover one row's 128B segment
#pragma unroll
            for (int i = 0; i < 8; ++i) {
                int row = rbase + i * 16;
                int gn = node0 + row; if (gn >= Nn) gn = Nn - 1;
                float4 v = *(const float4*)(X + (size_t)gn * CIN + kc * KC + lane8 * 4);
                float* d = &sX[row * 33 + lane8 * 4];
                d[0] = v.x; d[1] = v.y; d[2] = v.z; d[3] = v.w;
            }
            __syncthreads();
#pragma unroll 4
            for (int k = 0; k < KC; ++k) {
                const double* wp = (const double*)&sW[k * 64 + fc * 16];
                unsigned long long w[8];
#pragma unroll
                for (int p = 0; p < 8; ++p)
                    w[p] = __double_as_longlong(wp[p]);
#pragma unroll
                for (int j = 0; j < 4; ++j) {
                    float xs = sX[(nr * 4 + j) * 33 + k];
                    unsigned long long x2;
                    asm("mov.b64 %0, {%1, %1};" : "=l"(x2) : "r"(__float_as_uint(xs)));
#pragma unroll
                    for (int p = 0; p < 8; ++p)
                        asm("fma.rn.f32x2 %0, %1, %2, %0;"
                            : "+l"(acc[j][p]) : "l"(x2), "l"(w[p]));
                }
            }
            __syncthreads();
        }
#pragma unroll
        for (int j = 0; j < 4; ++j) {
            int gn = node0 + nr * 4 + j;
            if (gn < Nn) {
                float4* yr = (float4*)(Y + (size_t)gn * 64 + fc * 16);
#pragma unroll
                for (int q = 0; q < 4; ++q) {
                    unsigned long long a0 = acc[j][2 * q], a1 = acc[j][2 * q + 1];
                    float4 o;
                    o.x = __uint_as_float((unsigned)(a0 & 0xffffffffu));
                    o.y = __uint_as_float((unsigned)(a0 >> 32));
                    o.z = __uint_as_float((unsigned)(a1 & 0xffffffffu));
                    o.w = __uint_as_float((unsigned)(a1 >> 32));
                    yr[q] = o;
                }
            }
        }
    } else {
        int t = (blockIdx.x - 2 * MMB) * 128 + threadIdx.x;
        int e = t * 4;
        if (e >= ETOT) return;
        int d0, d1, d2, d3;
        if (e < Ecnt) {                       // Ecnt % 4 == 0: no straddle
            int4 dv = *(const int4*)(ei + Ecnt + e);
            d0 = dv.x; d1 = dv.y; d2 = dv.z; d3 = dv.w;
        } else {
            d0 = e - Ecnt; d1 = d0 + 1; d2 = d0 + 2; d3 = d0 + 3;
        }
        int4 offs;
        offs.x = atomicAdd(&g_deg[d0], 1);
        offs.y = atomicAdd(&g_deg[d1], 1);
        offs.z = atomicAdd(&g_deg[d2], 1);
        offs.w = atomicAdd(&g_deg[d3], 1);
        *(int4*)(g_eoff + e) = offs;
    }
}

// ---------------- scan: per-block partials, then redundant-scan finish ----
__global__ void __launch_bounds__(256) scanA_kernel() {
    __shared__ int ws[32];
    int i = blockIdx.x * 256 + threadIdx.x;
    int v = (i < Nn) ? g_deg[i] : 0;
    int excl = block_excl_scan(v, ws);
    if (threadIdx.x == 255) g_bsum[blockIdx.x] = excl + v;
}

__global__ void __launch_bounds__(512) scanB_kernel() {
    __shared__ int ws[32];
    __shared__ int sc[512];
    int t = threadIdx.x;
    int v = (t < NB) ? g_bsum[t] : 0;            // redundant scan of partials
    int excl = block_excl_scan(v, ws);
    sc[t] = excl;
    __syncthreads();
    int block_off = sc[blockIdx.x];
    __syncthreads();
    int i = blockIdx.x * 256 + t;                // only t<256 map to nodes
    int v2 = (t < 256 && i < Nn) ? g_deg[i] : 0;
    int excl2 = block_excl_scan(v2, ws);
    if (t < 256 && i < Nn) {
        int p = block_off + excl2;
        g_ptr[i] = p;
        g_end[i] = p + v2;
    }
}

// ---------------- scatter (atomic-free, vectorized) ----------------
__global__ void __launch_bounds__(128) scatter_kernel(const int* __restrict__ ei) {
    int t = blockIdx.x * 128 + threadIdx.x;
    int e = t * 4;
    if (e >= ETOT) return;
    int4 off4 = *(const int4*)(g_eoff + e);
    if (e < Ecnt) {
        int4 sv = *(const int4*)(ei + e);
        int4 dv = *(const int4*)(ei + Ecnt + e);
        g_srcA[g_ptr[dv.x] + off4.x] = sv.x;
        g_srcA[g_ptr[dv.y] + off4.y] = sv.y;
        g_srcA[g_ptr[dv.z] + off4.z] = sv.z;
        g_srcA[g_ptr[dv.w] + off4.w] = sv.w;
    } else {
        int b = e - Ecnt;
        g_srcA[g_ptr[b]     + off4.x] = b;
        g_srcA[g_ptr[b + 1] + off4.y] = b + 1;
        g_srcA[g_ptr[b + 2] + off4.z] = b + 2;
        g_srcA[g_ptr[b + 3] + off4.w] = b + 3;
    }
}

// ---------------- fused edge softmax + aggregate + epilogue ----------------
// One warp per destination node; two half-warps process 2 edges/iteration.
// Each sublane (0..15) covers 4 features (float4). src indices batch-loaded
// (32 at a time) and broadcast via shfl. No segment-max pass: logits bounded
// far below fp32 exp overflow for this distribution (clamped at 80 as safety).
template <int H, int RELU, int LAST, int ZNEXT>
__global__ void __launch_bounds__(256) gat_agg_kernel(
    const float* __restrict__ att, const float* __restrict__ bias,
    float* __restrict__ out_ext)
{
    constexpr int G4 = (Dh / H) / 4;        // sublanes per head (4 for H=4, 16 for H=1)
    int gid  = blockIdx.x * 256 + threadIdx.x;
    if (ZNEXT && gid < Nn) g_deg[gid] = 0;  // zero deg for next layer's hist
    int warp = gid >> 5;
    int lane = threadIdx.x & 31;
    int half = lane >> 4, sub = lane & 15;
    int n = warp;                           // grid == Nn warps exactly

    float4 xr4 = ((const float4*)g_xr)[n * 16 + sub];
    float4 at4 = ((const float4*)att)[sub];

    int beg = g_ptr[n];
    int nE  = g_end[n] - beg;               // >= 1 (self loop)

    float4 acc = make_float4(0.f, 0.f, 0.f, 0.f);
    float den = 0.f;

    for (int base = 0; base < nE; base += 32) {
        int rem = nE - base; if (rem > 32) rem = 32;
        int sb = (lane < rem) ? g_srcA[beg + base + lane] : 0;
        for (int k = 0; k < rem; k += 2) {
            int my = k + half;
            bool valid = my < rem;
            int src = __shfl_sync(0xffffffffu, sb, valid ? my : 0);
            float4 xl = valid ? ((const float4*)g_xl)[src * 16 + sub]
                              : make_float4(0.f, 0.f, 0.f, 0.f);
            float s0 = xl.x + xr4.x; s0 = fmaxf(s0, 0.2f * s0);
            float s1 = xl.y + xr4.y; s1 = fmaxf(s1, 0.2f * s1);
            float s2 = xl.z + xr4.z; s2 = fmaxf(s2, 0.2f * s2);
            float s3 = xl.w + xr4.w; s3 = fmaxf(s3, 0.2f * s3);
            float p = s0 * at4.x;
            p = fmaf(s1, at4.y, p);
            p = fmaf(s2, at4.z, p);
            p = fmaf(s3, at4.w, p);
#pragma unroll
            for (int off = 1; off < G4; off <<= 1)
                p += __shfl_xor_sync(0xffffffffu, p, off);
            float ev = valid ? __expf(fminf(p, 80.f)) : 0.f;
            den += ev;
            acc.x = fmaf(xl.x, ev, acc.x);
            acc.y = fmaf(xl.y, ev, acc.y);
            acc.z = fmaf(xl.z, ev, acc.z);
            acc.w = fmaf(xl.w, ev, acc.w);
        }
    }
    // combine the two half-warps (both halves end up with full sums)
    den   += __shfl_xor_sync(0xffffffffu, den,   16);
    acc.x += __shfl_xor_sync(0xffffffffu, acc.x, 16);
    acc.y += __shfl_xor_sync(0xffffffffu, acc.y, 16);
    acc.z += __shfl_xor_sync(0xffffffffu, acc.z, 16);
    acc.w += __shfl_xor_sync(0xffffffffu, acc.w, 16);

    float invd = 1.0f / (den + 1e-16f);
    float4 b4 = ((const float4*)bias)[sub];
    float vx = acc.x * invd + b4.x;
    float vy = acc.y * invd + b4.y;
    float vz = acc.z * invd + b4.z;
    float vw = acc.w * invd + b4.w;
    if (RELU) {
        vx = fmaxf(vx, 0.f); vy = fmaxf(vy, 0.f);
        vz = fmaxf(vz, 0.f); vw = fmaxf(vw, 0.f);
    }
    // L1 normalize over 64 features (identical across halves; reduce 16 sublanes)
    float s = fabsf(vx) + fabsf(vy) + fabsf(vz) + fabsf(vw);
#pragma unroll
    for (int off = 1; off < 16; off <<= 1) s += __shfl_xor_sync(0xffffffffu, s, off);
    float inv1 = 1.0f / fmaxf(s, 1e-12f);
    vx *= inv1; vy *= inv1; vz *= inv1; vw *= inv1;

    if (LAST) {   // L2 normalize + final relu
        float q = vx * vx + vy * vy + vz * vz + vw * vw;
#pragma unroll
        for (int off = 1; off < 16; off <<= 1) q += __shfl_xor_sync(0xffffffffu, q, off);
        float inv2 = 1.0f / fmaxf(sqrtf(q), 1e-12f);
        vx = fmaxf(vx * inv2, 0.f); vy = fmaxf(vy * inv2, 0.f);
        vz = fmaxf(vz * inv2, 0.f); vw = fmaxf(vw * inv2, 0.f);
    }
    float* outp = LAST ? out_ext : g_x;
    if (half == 0)
        ((float4*)outp)[n * 16 + sub] = make_float4(vx, vy, vz, vw);
}

// ---------------- host ----------------
extern "C" void kernel_launch(void* const* d_in, const int* in_sizes, int n_in,
                              void* d_out, int out_size)
{
    const float* x0  = (const float*)d_in[0];
    const int*   ei0 = (const int*)d_in[1];
    const int*   ei1 = (const int*)d_in[2];
    const int*   ei2 = (const int*)d_in[3];

    zero_deg_kernel<<<NB, 256>>>();

    // ---- layer 0 (CIN=128, H=4, relu) ----
    fusedA_kernel<128><<<2 * MMB + HISTB, 128>>>(
        x0, 0,
        (const float*)d_in[4], (const float*)d_in[5],
        (const float*)d_in[6], (const float*)d_in[7], ei0);
    scanA_kernel<<<NB, 256>>>();
    scanB_kernel<<<NB, 512>>>();
    scatter_kernel<<<HISTB, 128>>>(ei0);
    gat_agg_kernel<4, 1, 0, 1><<<AGGB, 256>>>(
        (const float*)d_in[8], (const float*)d_in[9], nullptr);

    // ---- layer 1 (CIN=64, H=4, relu) ----
    fusedA_kernel<64><<<2 * MMB + HISTB, 128>>>(
        nullptr, 1,
        (const float*)d_in[10], (const float*)d_in[11],
        (const float*)d_in[12], (const float*)d_in[13], ei1);
    scanA_kernel<<<NB, 256>>>();
    scanB_kernel<<<NB, 512>>>();
    scatter_kernel<<<HISTB, 128>>>(ei1);
    gat_agg_kernel<4, 1, 0, 1><<<AGGB, 256>>>(
        (const float*)d_in[14], (const float*)d_in[15], nullptr);

    // ---- layer 2 (CIN=64, H=1, no relu, + L2-norm + final relu) ----
    fusedA_kernel<64><<<2 * MMB + HISTB, 128>>>(
        nullptr, 1,
        (const float*)d_in[16], (const float*)d_in[17],
        (const float*)d_in[18], (const float*)d_in[19], ei2);
    scanA_kernel<<<NB, 256>>>();
    scanB_kernel<<<NB, 512>>>();
    scatter_kernel<<<HISTB, 128>>>(ei2);
    gat_agg_kernel<1, 0, 1, 0><<<AGGB, 256>>>(
        (const float*)d_in[20], (const float*)d_in[21], (float*)d_out);
}